// round 11
// baseline (speedup 1.0000x reference)
#include <cuda_runtime.h>
#include <cstdint>

#define T_STEPS 20
#define HID     128
#define BATCH   65536
#define M_TILE  64
#define THREADS 256
#define HPAD    68            // padded m-stride of transposed h buffer
#define HBUF    (128 * HPAD)  // 8704 floats per h buffer

// Shared memory layout (floats)
#define OFF_W    0                            // 2 bufs x [32k][4g][128d] = 32768
#define OFF_H    (OFF_W + 2 * 16384)          // 32768
#define OFF_OBS  (OFF_H + 2 * HBUF)           // 50176
#define OFF_WC   (OFF_OBS + T_STEPS * 128)    // 52736
#define OFF_BC   (OFF_WC + 1024)              // 53760
#define SMEM_FLOATS (OFF_BC + 512)            // 54272
#define SMEM_BYTES  (SMEM_FLOATS * 4)         // 217088 bytes

// Precomputed weights (device scratch; no runtime allocation allowed)
__device__ __align__(16) float g_Wt[4][128][128]; // [gate][k][d] = W_hh[(g*128+d)*128+k]
__device__ __align__(16) float g_Wc[2][512];      // combined obs->gate weights
__device__ __align__(16) float g_bc[512];         // combined bias

typedef unsigned long long u64t;

__device__ __forceinline__ u64t fma2(u64t a, u64t b, u64t c) {
    u64t d;
    asm("fma.rn.f32x2 %0, %1, %2, %3;" : "=l"(d) : "l"(a), "l"(b), "l"(c));
    return d;
}
__device__ __forceinline__ u64t pack2(float x) {
    u64t d;
    asm("mov.b64 %0, {%1, %1};" : "=l"(d) : "f"(x));
    return d;
}
__device__ __forceinline__ void unpack2(u64t v, float& lo, float& hi) {
    asm("mov.b64 {%0, %1}, %2;" : "=f"(lo), "=f"(hi) : "l"(v));
}

__device__ __forceinline__ void cp16(void* dst_smem, const void* src) {
    uint32_t d = (uint32_t)__cvta_generic_to_shared(dst_smem);
    asm volatile("cp.async.cg.shared.global [%0], [%1], 16;" :: "r"(d), "l"(src));
}
#define CP_COMMIT() asm volatile("cp.async.commit_group;" ::: "memory")
#define CP_WAIT1()  asm volatile("cp.async.wait_group 1;"  ::: "memory")
#define CP_WAIT0()  asm volatile("cp.async.wait_group 0;"  ::: "memory")

__device__ __forceinline__ float fsig(float x) {
    float e = __expf(-x);
    return __fdividef(1.0f, 1.0f + e);
}
__device__ __forceinline__ float ftanh(float x) {
    x = fminf(fmaxf(x, -15.0f), 15.0f);
    float e = __expf(-2.0f * x);
    return __fdividef(1.0f - e, 1.0f + e);
}

// ---------------------------------------------------------------------------
// Setup: fold embedding into gate weights; transpose W_hh per gate (k-major).
// ---------------------------------------------------------------------------
__global__ void setup_kernel(const float* __restrict__ W_emb, const float* __restrict__ b_emb,
                             const float* __restrict__ W_ih,  const float* __restrict__ W_hh,
                             const float* __restrict__ b_ih,  const float* __restrict__ b_hh) {
    int gid = blockIdx.x * blockDim.x + threadIdx.x;
    if (gid < 4 * 128 * 128) {
        int g = gid >> 14;
        int k = (gid >> 7) & 127;
        int d = gid & 127;
        g_Wt[g][k][d] = W_hh[(g * 128 + d) * 128 + k];
    }
    if (gid < 512) {
        float w0 = 0.f, w1 = 0.f, bb = 0.f;
        #pragma unroll 8
        for (int j = 0; j < 64; ++j) {
            float wij = W_ih[gid * 64 + j];
            w0 += wij * W_emb[j * 2 + 0];
            w1 += wij * W_emb[j * 2 + 1];
            bb += wij * b_emb[j];
        }
        g_Wc[0][gid] = w0;
        g_Wc[1][gid] = w1;
        g_bc[gid]    = bb + b_ih[gid] + b_hh[gid];
    }
}

// ---------------------------------------------------------------------------
// Main fused LSTM kernel (square 32m x 32d warp tiles, all gates per k).
// 8 warps tile (64m x 128d) as 2 m-halves x 4 d-quarters. Lane l owns
// d = 32*(w>>1)+4*(l&7)..+4 and m = 32*(w&1)+8*(l>>3)..+8 (4 f32x2 m-pairs),
// for ALL 4 gates -> acc[4][4][4] u64 (same 128-reg footprint as R10).
// Weight chunks are k-windows [32k][4g][128d], cp.async double-buffered.
// Per warp per k: 2 h LDS (bcast) + 4 w LDS (1 wf each) + 16 pack2 + 64 FFMA2
//   -> SM crossbar ~19% (vs 75% in R10), FMA-per-weight-load reuse 4x.
// No gate exchange: each lane has i,f,g,o for its own (m,d) patch.
// ---------------------------------------------------------------------------
__global__ void __launch_bounds__(THREADS, 1)
lstm_kernel(const float* __restrict__ obs, const float* __restrict__ h0,
            const float* __restrict__ c0, float* __restrict__ out) {
    extern __shared__ float smem[];
    float* sW   = smem + OFF_W;    // 2 x [32][4][128] weight chunks
    float* sH   = smem + OFF_H;    // 2 x [128][HPAD] transposed hidden state
    float* sObs = smem + OFF_OBS;  // [20][2][64]
    float* sWc  = smem + OFF_WC;   // [2][512]
    float* sBc  = smem + OFF_BC;   // [512]

    const int tid   = threadIdx.x;
    const int l     = tid & 31;
    const int w     = tid >> 5;
    const int laneD = 32 * (w >> 1) + 4 * (l & 7);  // lane's d base (4 d)
    const int laneM = 32 * (w & 1) + 8 * (l >> 3);  // lane's m base (8 m = 4 pairs)
    const int mBase = blockIdx.x * M_TILE;

    // --- Stage h0 (transposed), obs ([t][c][m]), combined weights/bias ---
    for (int idx = tid; idx < M_TILE * HID; idx += THREADS) {
        int m = idx >> 7, d = idx & 127;
        sH[d * HPAD + m] = h0[(size_t)(mBase + m) * HID + d];
    }
    for (int idx = tid; idx < T_STEPS * 128; idx += THREADS) {
        int t = idx >> 7, r = idx & 127;
        int c = r >> 6, m = r & 63;
        sObs[idx] = obs[((size_t)t * BATCH + mBase + m) * 2 + c];
    }
    for (int idx = tid; idx < 1024; idx += THREADS) sWc[idx] = (&g_Wc[0][0])[idx];
    for (int idx = tid; idx < 512;  idx += THREADS) sBc[idx] = g_bc[idx];

    // --- c0 into registers: cc[mi][j], m = laneM+mi, d = laneD+j ---
    float cc[8][4];
    #pragma unroll
    for (int mi = 0; mi < 8; ++mi) {
        float4 a = *(const float4*)&c0[(size_t)(mBase + laneM + mi) * HID + laneD];
        cc[mi][0] = a.x; cc[mi][1] = a.y; cc[mi][2] = a.z; cc[mi][3] = a.w;
    }

    // --- Prefetch k-window 0 into weight buffer 0: dst [kk][g][d] ---
    #pragma unroll
    for (int i = 0; i < 16; ++i) {
        int lin = tid + i * 256;
        int kk = lin >> 7, rem = lin & 127;
        int g2 = rem >> 5, dq = rem & 31;
        cp16(sW + kk * 512 + g2 * 128 + dq * 4, &g_Wt[g2][kk][dq * 4]);
    }
    CP_COMMIT();
    __syncthreads();

    int hcur = 0;
    u64t acc[4][4][4]; // [gate][mp][j]: pair (m=laneM+2mp, m+1), d = laneD+j

    for (int t = 0; t < T_STEPS; ++t) {
        // --- init gates: bias + 2-wide obs projection (m-pairs from sObs) ---
        {
            const float* ob = sObs + t * 128 + laneM;
            ulonglong2 a0 = *(const ulonglong2*)(ob);        // comp0 pairs 0,1
            ulonglong2 a1 = *(const ulonglong2*)(ob + 4);    // comp0 pairs 2,3
            ulonglong2 b0 = *(const ulonglong2*)(ob + 64);   // comp1 pairs 0,1
            ulonglong2 b1 = *(const ulonglong2*)(ob + 68);   // comp1 pairs 2,3
            u64t o0[4] = {a0.x, a0.y, a1.x, a1.y};
            u64t o1[4] = {b0.x, b0.y, b1.x, b1.y};
            #pragma unroll
            for (int g = 0; g < 4; ++g) {
                int n = g * 128 + laneD;
                float4 bv  = *(const float4*)&sBc[n];
                float4 wa  = *(const float4*)&sWc[n];
                float4 wbv = *(const float4*)&sWc[512 + n];
                u64t bd[4]  = {pack2(bv.x),  pack2(bv.y),  pack2(bv.z),  pack2(bv.w)};
                u64t wdA[4] = {pack2(wa.x),  pack2(wa.y),  pack2(wa.z),  pack2(wa.w)};
                u64t wdB[4] = {pack2(wbv.x), pack2(wbv.y), pack2(wbv.z), pack2(wbv.w)};
                #pragma unroll
                for (int mp = 0; mp < 4; ++mp) {
                    #pragma unroll
                    for (int j = 0; j < 4; ++j)
                        acc[g][mp][j] = fma2(o1[mp], wdB[j], fma2(o0[mp], wdA[j], bd[j]));
                }
            }
        }

        // --- recurrent GEMM: 4 k-windows of 32, cp.async double buffered ---
        int buf = 0;
        #pragma unroll
        for (int c = 0; c < 4; ++c) {
            __syncthreads();   // prior window's reads done; h writes (prev step) visible
            {
                int nkb = ((c + 1) & 3) * 32;   // at c=3: window 0 for next step
                float* dst = sW + (buf ^ 1) * 16384;
                #pragma unroll
                for (int i = 0; i < 16; ++i) {
                    int lin = tid + i * 256;
                    int kk = lin >> 7, rem = lin & 127;
                    int g2 = rem >> 5, dq = rem & 31;
                    cp16(dst + kk * 512 + g2 * 128 + dq * 4, &g_Wt[g2][nkb + kk][dq * 4]);
                }
                CP_COMMIT();
                CP_WAIT1();    // current window's group complete (own thread)
            }
            __syncthreads();   // all threads' cp.async for current window visible

            const float* wb = sW + buf * 16384;
            const float* hb = sH + hcur * HBUF + c * 32 * HPAD + laneM;
            #pragma unroll 2
            for (int kk = 0; kk < 32; ++kk) {
                ulonglong2 hA = *(const ulonglong2*)(hb + kk * HPAD);      // pairs 0,1
                ulonglong2 hB = *(const ulonglong2*)(hb + kk * HPAD + 4);  // pairs 2,3
                const float* wr = wb + kk * 512 + laneD;
                #pragma unroll
                for (int g = 0; g < 4; ++g) {
                    float4 wv = *(const float4*)(wr + g * 128);
                    u64t w0 = pack2(wv.x), w1 = pack2(wv.y), w2 = pack2(wv.z), w3 = pack2(wv.w);
                    acc[g][0][0] = fma2(hA.x, w0, acc[g][0][0]);
                    acc[g][0][1] = fma2(hA.x, w1, acc[g][0][1]);
                    acc[g][0][2] = fma2(hA.x, w2, acc[g][0][2]);
                    acc[g][0][3] = fma2(hA.x, w3, acc[g][0][3]);
                    acc[g][1][0] = fma2(hA.y, w0, acc[g][1][0]);
                    acc[g][1][1] = fma2(hA.y, w1, acc[g][1][1]);
                    acc[g][1][2] = fma2(hA.y, w2, acc[g][1][2]);
                    acc[g][1][3] = fma2(hA.y, w3, acc[g][1][3]);
                    acc[g][2][0] = fma2(hB.x, w0, acc[g][2][0]);
                    acc[g][2][1] = fma2(hB.x, w1, acc[g][2][1]);
                    acc[g][2][2] = fma2(hB.x, w2, acc[g][2][2]);
                    acc[g][2][3] = fma2(hB.x, w3, acc[g][2][3]);
                    acc[g][3][0] = fma2(hB.y, w0, acc[g][3][0]);
                    acc[g][3][1] = fma2(hB.y, w1, acc[g][3][1]);
                    acc[g][3][2] = fma2(hB.y, w2, acc[g][3][2]);
                    acc[g][3][3] = fma2(hB.y, w3, acc[g][3][3]);
                }
            }
            buf ^= 1;
        }

        // --- elementwise LSTM update; write h_new into the other buffer ---
        int hnxt = hcur ^ 1;
        float* hw = sH + hnxt * HBUF;
        #pragma unroll
        for (int j = 0; j < 4; ++j) {
            int d = laneD + j;
            float hv[8];
            #pragma unroll
            for (int mp = 0; mp < 4; ++mp) {
                float i0, i1, f0, f1, g0, g1, o0, o1;
                unpack2(acc[0][mp][j], i0, i1);
                unpack2(acc[1][mp][j], f0, f1);
                unpack2(acc[2][mp][j], g0, g1);
                unpack2(acc[3][mp][j], o0, o1);
                {
                    float cn = fsig(f0) * cc[2 * mp][j] + fsig(i0) * ftanh(g0);
                    cc[2 * mp][j] = cn;
                    hv[2 * mp] = fsig(o0) * ftanh(cn);
                }
                {
                    float cn = fsig(f1) * cc[2 * mp + 1][j] + fsig(i1) * ftanh(g1);
                    cc[2 * mp + 1][j] = cn;
                    hv[2 * mp + 1] = fsig(o1) * ftanh(cn);
                }
            }
            *(float4*)(hw + d * HPAD + laneM)     = make_float4(hv[0], hv[1], hv[2], hv[3]);
            *(float4*)(hw + d * HPAD + laneM + 4) = make_float4(hv[4], hv[5], hv[6], hv[7]);
        }
        hcur = hnxt;
        // next iteration's first __syncthreads orders these writes before reads
    }

    CP_WAIT0();
    __syncthreads();

    // --- write final h (coalesced along d) ---
    const float* hf = sH + hcur * HBUF;
    for (int idx = tid; idx < M_TILE * HID; idx += THREADS) {
        int m = idx >> 7, d = idx & 127;
        out[(size_t)(mBase + m) * HID + d] = hf[d * HPAD + m];
    }
}

extern "C" void kernel_launch(void* const* d_in, const int* in_sizes, int n_in,
                              void* d_out, int out_size) {
    const float* obs   = (const float*)d_in[0];
    const float* h0    = (const float*)d_in[1];
    const float* c0    = (const float*)d_in[2];
    const float* W_emb = (const float*)d_in[3];
    const float* b_emb = (const float*)d_in[4];
    const float* W_ih  = (const float*)d_in[5];
    const float* W_hh  = (const float*)d_in[6];
    const float* b_ih  = (const float*)d_in[7];
    const float* b_hh  = (const float*)d_in[8];
    float* out = (float*)d_out;

    (void)in_sizes; (void)n_in; (void)out_size;

    setup_kernel<<<256, 256>>>(W_emb, b_emb, W_ih, W_hh, b_ih, b_hh);

    cudaFuncSetAttribute(lstm_kernel, cudaFuncAttributeMaxDynamicSharedMemorySize, SMEM_BYTES);
    lstm_kernel<<<BATCH / M_TILE, THREADS, SMEM_BYTES>>>(obs, h0, c0, out);
}

// round 14
// speedup vs baseline: 1.2110x; 1.2110x over previous
#include <cuda_runtime.h>
#include <cstdint>

#define T_STEPS 20
#define HID     128
#define BATCH   65536
#define M_TILE  64
#define THREADS 256
#define HPAD    68            // padded m-stride of transposed h buffer
#define HBUF    (128 * HPAD)  // 8704 floats per h buffer

// Shared memory layout (floats)
#define OFF_W    0                            // 2 bufs x [32k][4g][128d] = 32768
#define OFF_H    (OFF_W + 2 * 16384)          // 32768
#define OFF_OBS  (OFF_H + 2 * HBUF)           // 50176
#define OFF_WC   (OFF_OBS + T_STEPS * 128)    // 52736
#define OFF_BC   (OFF_WC + 1024)              // 53760
#define SMEM_FLOATS (OFF_BC + 512)            // 54272
#define SMEM_BYTES  (SMEM_FLOATS * 4)         // 217088 bytes

// Precomputed weights (device scratch; no runtime allocation allowed)
__device__ __align__(16) float g_Wt[4][128][128]; // [gate][k][d] = W_hh[(g*128+d)*128+k]
__device__ __align__(16) float g_Wc[2][512];      // combined obs->gate weights
__device__ __align__(16) float g_bc[512];         // combined bias

typedef unsigned long long u64t;

__device__ __forceinline__ u64t fma2(u64t a, u64t b, u64t c) {
    u64t d;
    asm("fma.rn.f32x2 %0, %1, %2, %3;" : "=l"(d) : "l"(a), "l"(b), "l"(c));
    return d;
}
__device__ __forceinline__ u64t pack2(float x) {
    u64t d;
    asm("mov.b64 %0, {%1, %1};" : "=l"(d) : "f"(x));
    return d;
}
__device__ __forceinline__ void unpack2(u64t v, float& lo, float& hi) {
    asm("mov.b64 {%0, %1}, %2;" : "=f"(lo), "=f"(hi) : "l"(v));
}

__device__ __forceinline__ void cp16(void* dst_smem, const void* src) {
    uint32_t d = (uint32_t)__cvta_generic_to_shared(dst_smem);
    asm volatile("cp.async.cg.shared.global [%0], [%1], 16;" :: "r"(d), "l"(src));
}
#define CP_COMMIT() asm volatile("cp.async.commit_group;" ::: "memory")
#define CP_WAIT1()  asm volatile("cp.async.wait_group 1;"  ::: "memory")
#define CP_WAIT0()  asm volatile("cp.async.wait_group 0;"  ::: "memory")

__device__ __forceinline__ float fsig(float x) {
    float e = __expf(-x);
    return __fdividef(1.0f, 1.0f + e);
}
__device__ __forceinline__ float ftanh(float x) {
    x = fminf(fmaxf(x, -15.0f), 15.0f);
    float e = __expf(-2.0f * x);
    return __fdividef(1.0f - e, 1.0f + e);
}

// ---------------------------------------------------------------------------
// Setup: fold embedding into gate weights; transpose W_hh per gate (k-major).
// ---------------------------------------------------------------------------
__global__ void setup_kernel(const float* __restrict__ W_emb, const float* __restrict__ b_emb,
                             const float* __restrict__ W_ih,  const float* __restrict__ W_hh,
                             const float* __restrict__ b_ih,  const float* __restrict__ b_hh) {
    int gid = blockIdx.x * blockDim.x + threadIdx.x;
    if (gid < 4 * 128 * 128) {
        int g = gid >> 14;
        int k = (gid >> 7) & 127;
        int d = gid & 127;
        g_Wt[g][k][d] = W_hh[(g * 128 + d) * 128 + k];
    }
    if (gid < 512) {
        float w0 = 0.f, w1 = 0.f, bb = 0.f;
        #pragma unroll 8
        for (int j = 0; j < 64; ++j) {
            float wij = W_ih[gid * 64 + j];
            w0 += wij * W_emb[j * 2 + 0];
            w1 += wij * W_emb[j * 2 + 1];
            bb += wij * b_emb[j];
        }
        g_Wc[0][gid] = w0;
        g_Wc[1][gid] = w1;
        g_bc[gid]    = bb + b_ih[gid] + b_hh[gid];
    }
}

// ---------------------------------------------------------------------------
// Main fused LSTM kernel (square 32m x 32d warp tiles, f32x2 paired over d).
// 8 warps tile (64m x 128d) as 2 m-halves x 4 d-quarters. Lane l owns
// m = 32*(w&1)+8*(l>>3)..+8 and d = 32*(w>>1)+4*(l&7)..+4 (2 d-pairs),
// for ALL 4 gates -> acc[4][8][2] u64 (128 regs, invariant).
// d-pairing means: weights load as NATIVE u64 d-pairs (no pack2/no float4
// temps); only h needs pack2 (8 MOVs/k), amortized across the 4 gates in a
// persistent hp[8]. Per-k transient set ~20 regs (R10-sized) with R11's
// crossbar profile (6 wf/warp/k vs 256 FMA-cyc budget).
// ---------------------------------------------------------------------------
__global__ void __launch_bounds__(THREADS, 1)
lstm_kernel(const float* __restrict__ obs, const float* __restrict__ h0,
            const float* __restrict__ c0, float* __restrict__ out) {
    extern __shared__ float smem[];
    float* sW   = smem + OFF_W;    // 2 x [32][4][128] weight chunks
    float* sH   = smem + OFF_H;    // 2 x [128][HPAD] transposed hidden state
    float* sObs = smem + OFF_OBS;  // [20][2][64]
    float* sWc  = smem + OFF_WC;   // [2][512]
    float* sBc  = smem + OFF_BC;   // [512]

    const int tid   = threadIdx.x;
    const int l     = tid & 31;
    const int w     = tid >> 5;
    const int laneD = 32 * (w >> 1) + 4 * (l & 7);  // lane's d base (4 d = 2 pairs)
    const int laneM = 32 * (w & 1) + 8 * (l >> 3);  // lane's m base (8 m)
    const int mBase = blockIdx.x * M_TILE;

    // --- Stage h0 (transposed), obs ([t][c][m]), combined weights/bias ---
    for (int idx = tid; idx < M_TILE * HID; idx += THREADS) {
        int m = idx >> 7, d = idx & 127;
        sH[d * HPAD + m] = h0[(size_t)(mBase + m) * HID + d];
    }
    for (int idx = tid; idx < T_STEPS * 128; idx += THREADS) {
        int t = idx >> 7, r = idx & 127;
        int c = r >> 6, m = r & 63;
        sObs[idx] = obs[((size_t)t * BATCH + mBase + m) * 2 + c];
    }
    for (int idx = tid; idx < 1024; idx += THREADS) sWc[idx] = (&g_Wc[0][0])[idx];
    for (int idx = tid; idx < 512;  idx += THREADS) sBc[idx] = g_bc[idx];

    // --- c0 into registers: cc[mi][j], m = laneM+mi, d = laneD+j ---
    float cc[8][4];
    #pragma unroll
    for (int mi = 0; mi < 8; ++mi) {
        float4 a = *(const float4*)&c0[(size_t)(mBase + laneM + mi) * HID + laneD];
        cc[mi][0] = a.x; cc[mi][1] = a.y; cc[mi][2] = a.z; cc[mi][3] = a.w;
    }

    // --- Prefetch k-window 0 into weight buffer 0: dst [kk][g][d] ---
    #pragma unroll
    for (int i = 0; i < 16; ++i) {
        int lin = tid + i * 256;
        int kk = lin >> 7, rem = lin & 127;
        int g2 = rem >> 5, dq = rem & 31;
        cp16(sW + kk * 512 + g2 * 128 + dq * 4, &g_Wt[g2][kk][dq * 4]);
    }
    CP_COMMIT();
    __syncthreads();

    int hcur = 0;
    u64t acc[4][8][2]; // [gate][mi][dp]: d-pair (laneD+2dp, +1), m = laneM+mi

    for (int t = 0; t < T_STEPS; ++t) {
        // --- init gates: bias + 2-wide obs projection ---
        {
            const float* ob = sObs + t * 128 + laneM;
            float4 oa0 = *(const float4*)(ob);          // comp0 m 0..3
            float4 oa1 = *(const float4*)(ob + 4);      // comp0 m 4..7
            float4 ob0 = *(const float4*)(ob + 64);     // comp1 m 0..3
            float4 ob1 = *(const float4*)(ob + 68);     // comp1 m 4..7
            u64t o0p[8] = {pack2(oa0.x), pack2(oa0.y), pack2(oa0.z), pack2(oa0.w),
                           pack2(oa1.x), pack2(oa1.y), pack2(oa1.z), pack2(oa1.w)};
            u64t o1p[8] = {pack2(ob0.x), pack2(ob0.y), pack2(ob0.z), pack2(ob0.w),
                           pack2(ob1.x), pack2(ob1.y), pack2(ob1.z), pack2(ob1.w)};
            #pragma unroll
            for (int g = 0; g < 4; ++g) {
                int n = g * 128 + laneD;
                ulonglong2 bd = *(const ulonglong2*)&sBc[n];          // native d-pairs
                ulonglong2 wA = *(const ulonglong2*)&sWc[n];
                ulonglong2 wB = *(const ulonglong2*)&sWc[512 + n];
                #pragma unroll
                for (int mi = 0; mi < 8; ++mi) {
                    acc[g][mi][0] = fma2(o1p[mi], wB.x, fma2(o0p[mi], wA.x, bd.x));
                    acc[g][mi][1] = fma2(o1p[mi], wB.y, fma2(o0p[mi], wA.y, bd.y));
                }
            }
        }

        // --- recurrent GEMM: 4 k-windows of 32, cp.async double buffered ---
        int buf = 0;
        #pragma unroll
        for (int c = 0; c < 4; ++c) {
            __syncthreads();   // prior window's reads done; h writes (prev step) visible
            {
                int nkb = ((c + 1) & 3) * 32;   // at c=3: window 0 for next step
                float* dst = sW + (buf ^ 1) * 16384;
                #pragma unroll
                for (int i = 0; i < 16; ++i) {
                    int lin = tid + i * 256;
                    int kk = lin >> 7, rem = lin & 127;
                    int g2 = rem >> 5, dq = rem & 31;
                    cp16(dst + kk * 512 + g2 * 128 + dq * 4, &g_Wt[g2][nkb + kk][dq * 4]);
                }
                CP_COMMIT();
                CP_WAIT1();    // current window's group complete (own thread)
            }
            __syncthreads();   // all threads' cp.async for current window visible

            const float* wb = sW + buf * 16384;
            const float* hb = sH + hcur * HBUF + c * 32 * HPAD + laneM;
            #pragma unroll 2
            for (int kk = 0; kk < 32; ++kk) {
                float4 ha = *(const float4*)(hb + kk * HPAD);      // h[m..m+3]
                float4 hc = *(const float4*)(hb + kk * HPAD + 4);  // h[m+4..m+7]
                u64t hp[8] = {pack2(ha.x), pack2(ha.y), pack2(ha.z), pack2(ha.w),
                              pack2(hc.x), pack2(hc.y), pack2(hc.z), pack2(hc.w)};
                const float* wr = wb + kk * 512 + laneD;
                #pragma unroll
                for (int g = 0; g < 4; ++g) {
                    ulonglong2 wd = *(const ulonglong2*)(wr + g * 128);  // native d-pairs
                    #pragma unroll
                    for (int mi = 0; mi < 8; ++mi) {
                        acc[g][mi][0] = fma2(hp[mi], wd.x, acc[g][mi][0]);
                        acc[g][mi][1] = fma2(hp[mi], wd.y, acc[g][mi][1]);
                    }
                }
            }
            buf ^= 1;
        }

        // --- elementwise LSTM update; write h_new into the other buffer ---
        int hnxt = hcur ^ 1;
        float* hw = sH + hnxt * HBUF;
        #pragma unroll
        for (int dp = 0; dp < 2; ++dp) {
            float h0v[8], h1v[8];
            int j = 2 * dp;
            #pragma unroll
            for (int mi = 0; mi < 8; ++mi) {
                float i0, i1, f0, f1, g0, g1, o0, o1;
                unpack2(acc[0][mi][dp], i0, i1);
                unpack2(acc[1][mi][dp], f0, f1);
                unpack2(acc[2][mi][dp], g0, g1);
                unpack2(acc[3][mi][dp], o0, o1);
                {
                    float cn = fsig(f0) * cc[mi][j] + fsig(i0) * ftanh(g0);
                    cc[mi][j] = cn;
                    h0v[mi] = fsig(o0) * ftanh(cn);
                }
                {
                    float cn = fsig(f1) * cc[mi][j + 1] + fsig(i1) * ftanh(g1);
                    cc[mi][j + 1] = cn;
                    h1v[mi] = fsig(o1) * ftanh(cn);
                }
            }
            int d0 = laneD + 2 * dp;
            *(float4*)(hw + d0 * HPAD + laneM)           = make_float4(h0v[0], h0v[1], h0v[2], h0v[3]);
            *(float4*)(hw + d0 * HPAD + laneM + 4)       = make_float4(h0v[4], h0v[5], h0v[6], h0v[7]);
            *(float4*)(hw + (d0 + 1) * HPAD + laneM)     = make_float4(h1v[0], h1v[1], h1v[2], h1v[3]);
            *(float4*)(hw + (d0 + 1) * HPAD + laneM + 4) = make_float4(h1v[4], h1v[5], h1v[6], h1v[7]);
        }
        hcur = hnxt;
        // next iteration's first __syncthreads orders these writes before reads
    }

    CP_WAIT0();
    __syncthreads();

    // --- write final h (coalesced along d) ---
    const float* hf = sH + hcur * HBUF;
    for (int idx = tid; idx < M_TILE * HID; idx += THREADS) {
        int m = idx >> 7, d = idx & 127;
        out[(size_t)(mBase + m) * HID + d] = hf[d * HPAD + m];
    }
}

extern "C" void kernel_launch(void* const* d_in, const int* in_sizes, int n_in,
                              void* d_out, int out_size) {
    const float* obs   = (const float*)d_in[0];
    const float* h0    = (const float*)d_in[1];
    const float* c0    = (const float*)d_in[2];
    const float* W_emb = (const float*)d_in[3];
    const float* b_emb = (const float*)d_in[4];
    const float* W_ih  = (const float*)d_in[5];
    const float* W_hh  = (const float*)d_in[6];
    const float* b_ih  = (const float*)d_in[7];
    const float* b_hh  = (const float*)d_in[8];
    float* out = (float*)d_out;

    (void)in_sizes; (void)n_in; (void)out_size;

    setup_kernel<<<256, 256>>>(W_emb, b_emb, W_ih, W_hh, b_ih, b_hh);

    cudaFuncSetAttribute(lstm_kernel, cudaFuncAttributeMaxDynamicSharedMemorySize, SMEM_BYTES);
    lstm_kernel<<<BATCH / M_TILE, THREADS, SMEM_BYTES>>>(obs, h0, c0, out);
}

// round 15
// speedup vs baseline: 1.3160x; 1.0867x over previous
#include <cuda_runtime.h>
#include <cstdint>

#define T_STEPS 20
#define HID     128
#define BATCH   65536
#define M_TILE  64
#define THREADS 256
#define HPAD    68            // padded m-stride of transposed h buffer
#define HBUF    (128 * HPAD)  // 8704 floats per h buffer

// Shared memory layout (floats)
#define OFF_W    0
#define OFF_H    (OFF_W + 2 * 16384)          // 32768
#define OFF_OBS  (OFF_H + 2 * HBUF)           // 50176
#define OFF_WC   (OFF_OBS + T_STEPS * 128)    // 52736
#define OFF_BC   (OFF_WC + 1024)              // 53760
#define SMEM_FLOATS (OFF_BC + 512)            // 54272
#define SMEM_BYTES  (SMEM_FLOATS * 4)         // 217088 bytes

// Precomputed weights (device scratch; no runtime allocation allowed)
__device__ __align__(16) float g_Wt[4][128][128]; // [gate][k][d] = W_hh[(g*128+d)*128+k]
__device__ __align__(16) float g_Wc[2][512];      // combined obs->gate weights
__device__ __align__(16) float g_bc[512];         // combined bias

typedef unsigned long long u64t;

__device__ __forceinline__ u64t fma2(u64t a, u64t b, u64t c) {
    u64t d;
    asm("fma.rn.f32x2 %0, %1, %2, %3;" : "=l"(d) : "l"(a), "l"(b), "l"(c));
    return d;
}
__device__ __forceinline__ u64t pack2(float x) {
    u64t d;
    asm("mov.b64 %0, {%1, %1};" : "=l"(d) : "f"(x));
    return d;
}
__device__ __forceinline__ void unpack2(u64t v, float& lo, float& hi) {
    asm("mov.b64 {%0, %1}, %2;" : "=f"(lo), "=f"(hi) : "l"(v));
}

__device__ __forceinline__ void cp16(void* dst_smem, const void* src) {
    uint32_t d = (uint32_t)__cvta_generic_to_shared(dst_smem);
    asm volatile("cp.async.cg.shared.global [%0], [%1], 16;" :: "r"(d), "l"(src));
}
#define CP_COMMIT() asm volatile("cp.async.commit_group;" ::: "memory")
#define CP_WAIT1()  asm volatile("cp.async.wait_group 1;"  ::: "memory")
#define CP_WAIT0()  asm volatile("cp.async.wait_group 0;"  ::: "memory")

__device__ __forceinline__ float fsig(float x) {
    float e = __expf(-x);
    return __fdividef(1.0f, 1.0f + e);
}
__device__ __forceinline__ float ftanh(float x) {
    x = fminf(fmaxf(x, -15.0f), 15.0f);
    float e = __expf(-2.0f * x);
    return __fdividef(1.0f - e, 1.0f + e);
}

// ---------------------------------------------------------------------------
// Setup: fold embedding into gate weights; transpose W_hh per gate (k-major).
// ---------------------------------------------------------------------------
__global__ void setup_kernel(const float* __restrict__ W_emb, const float* __restrict__ b_emb,
                             const float* __restrict__ W_ih,  const float* __restrict__ W_hh,
                             const float* __restrict__ b_ih,  const float* __restrict__ b_hh) {
    int gid = blockIdx.x * blockDim.x + threadIdx.x;
    if (gid < 4 * 128 * 128) {
        int g = gid >> 14;
        int k = (gid >> 7) & 127;
        int d = gid & 127;
        g_Wt[g][k][d] = W_hh[(g * 128 + d) * 128 + k];
    }
    if (gid < 512) {
        float w0 = 0.f, w1 = 0.f, bb = 0.f;
        #pragma unroll 8
        for (int j = 0; j < 64; ++j) {
            float wij = W_ih[gid * 64 + j];
            w0 += wij * W_emb[j * 2 + 0];
            w1 += wij * W_emb[j * 2 + 1];
            bb += wij * b_emb[j];
        }
        g_Wc[0][gid] = w0;
        g_Wc[1][gid] = w1;
        g_bc[gid]    = bb + b_ih[gid] + b_hh[gid];
    }
}

// ---------------------------------------------------------------------------
// Main fused LSTM kernel: R10 loop structure, 32m x 32d warp tiles.
// 8 warps tile (64m x 128d) as 2 m-halves x 4 d-quarters:
//   wq = w & 3 (d-quarter), wh = w >> 2 (m-half)
//   lane owns m = 32*wh + 8*(l>>3) .. +8 (4 f32x2 m-pairs), d = 32*wq + 4*(l&7) .. +4
// One gate per chunk (register-stable schedule, proven in R10); per warp per k:
//   2 LDS h (native u64 m-pairs, 1 wf each) + 1 LDS.128 w (1 wf, was 4) +
//   4 pack2 + 16 FFMA2  ->  SM crossbar 37% of FMA wall (was 75% in R10).
// acc[4][4][4] m-paired, per-k transients ~20 regs: identical to R10.
// ---------------------------------------------------------------------------
__global__ void __launch_bounds__(THREADS, 1)
lstm_kernel(const float* __restrict__ obs, const float* __restrict__ h0,
            const float* __restrict__ c0, float* __restrict__ out) {
    extern __shared__ float smem[];
    float* sW   = smem + OFF_W;    // 2 x [128][128]  gate-chunk weights, k-major
    float* sH   = smem + OFF_H;    // 2 x [128][HPAD] transposed hidden state
    float* sObs = smem + OFF_OBS;  // [20][2][64]  (component-major for m-pair loads)
    float* sWc  = smem + OFF_WC;   // [2][512]
    float* sBc  = smem + OFF_BC;   // [512]

    const int tid   = threadIdx.x;
    const int l     = tid & 31;
    const int w     = tid >> 5;
    const int laneD = 32 * (w & 3) + 4 * (l & 7);   // d base (4 d)
    const int laneM = 32 * (w >> 2) + 8 * (l >> 3); // m base (8 m = 4 pairs)
    const int mBase = blockIdx.x * M_TILE;

    // --- Stage h0 (transposed), obs ([t][c][m]), combined weights/bias ---
    for (int idx = tid; idx < M_TILE * HID; idx += THREADS) {
        int m = idx >> 7, d = idx & 127;
        sH[d * HPAD + m] = h0[(size_t)(mBase + m) * HID + d];
    }
    for (int idx = tid; idx < T_STEPS * 128; idx += THREADS) {
        int t = idx >> 7, r = idx & 127;
        int c = r >> 6, m = r & 63;
        sObs[idx] = obs[((size_t)t * BATCH + mBase + m) * 2 + c];
    }
    for (int idx = tid; idx < 1024; idx += THREADS) sWc[idx] = (&g_Wc[0][0])[idx];
    for (int idx = tid; idx < 512;  idx += THREADS) sBc[idx] = g_bc[idx];

    // --- c0 into registers: cc[mi][j], m = laneM+mi, d = laneD+j ---
    float cc[8][4];
    #pragma unroll
    for (int mi = 0; mi < 8; ++mi) {
        float4 a = *(const float4*)&c0[(size_t)(mBase + laneM + mi) * HID + laneD];
        cc[mi][0] = a.x; cc[mi][1] = a.y; cc[mi][2] = a.z; cc[mi][3] = a.w;
    }

    // --- Prefetch gate chunk 0 into weight buffer 0 ---
    {
        const float4* src = (const float4*)&g_Wt[0][0][0];
        float* dst = sW;
        #pragma unroll
        for (int i = 0; i < 16; ++i)
            cp16(dst + (tid + i * 256) * 4, src + tid + i * 256);
        CP_COMMIT();
    }
    __syncthreads();

    int hcur = 0;
    u64t acc[4][4][4]; // [gate][mp][j]: pair (m=laneM+2mp, m+1), d = laneD+j

    for (int t = 0; t < T_STEPS; ++t) {
        // --- init gates: bias + 2-wide obs projection (m-pairs from sObs) ---
        {
            u64t o0[4], o1[4];
            const float* ob = sObs + t * 128 + laneM;
            #pragma unroll
            for (int mp = 0; mp < 4; ++mp) {
                o0[mp] = *(const u64t*)(ob + 2 * mp);       // comp 0, m-pair
                o1[mp] = *(const u64t*)(ob + 64 + 2 * mp);  // comp 1, m-pair
            }
            #pragma unroll
            for (int g = 0; g < 4; ++g) {
                int n = g * 128 + laneD;
                float4 bv = *(const float4*)&sBc[n];
                float4 wa = *(const float4*)&sWc[n];
                float4 wbv = *(const float4*)&sWc[512 + n];
                u64t bd[4]  = {pack2(bv.x),  pack2(bv.y),  pack2(bv.z),  pack2(bv.w)};
                u64t wdA[4] = {pack2(wa.x),  pack2(wa.y),  pack2(wa.z),  pack2(wa.w)};
                u64t wdB[4] = {pack2(wbv.x), pack2(wbv.y), pack2(wbv.z), pack2(wbv.w)};
                #pragma unroll
                for (int mp = 0; mp < 4; ++mp) {
                    #pragma unroll
                    for (int j = 0; j < 4; ++j)
                        acc[g][mp][j] = fma2(o1[mp], wdB[j], fma2(o0[mp], wdA[j], bd[j]));
                }
            }
        }

        // --- recurrent GEMM: 4 gate chunks, K=128, cp.async double buffered ---
        #pragma unroll
        for (int g = 0; g < 4; ++g) {
            __syncthreads();   // prior chunk's reads done; h writes (prev step) visible
            {
                const float4* src = (const float4*)&g_Wt[(g + 1) & 3][0][0];
                float* dst = sW + ((g + 1) & 1) * 16384;
                #pragma unroll
                for (int i = 0; i < 16; ++i)
                    cp16(dst + (tid + i * 256) * 4, src + tid + i * 256);
                CP_COMMIT();
                CP_WAIT1();    // current chunk's group complete (own thread)
            }
            __syncthreads();   // all threads' cp.async for current chunk visible

            const float* wb = sW + (g & 1) * 16384;
            const float* hb = sH + hcur * HBUF + laneM;
            #pragma unroll 8
            for (int k = 0; k < 128; ++k) {
                ulonglong2 hA = *(const ulonglong2*)(hb + k * HPAD);      // pairs (m0,m1),(m2,m3)
                ulonglong2 hB = *(const ulonglong2*)(hb + k * HPAD + 4);  // pairs (m4,m5),(m6,m7)
                float4 wv = *(const float4*)(wb + k * 128 + laneD);
                u64t w0 = pack2(wv.x), w1 = pack2(wv.y), w2 = pack2(wv.z), w3 = pack2(wv.w);
                acc[g][0][0] = fma2(hA.x, w0, acc[g][0][0]);
                acc[g][0][1] = fma2(hA.x, w1, acc[g][0][1]);
                acc[g][0][2] = fma2(hA.x, w2, acc[g][0][2]);
                acc[g][0][3] = fma2(hA.x, w3, acc[g][0][3]);
                acc[g][1][0] = fma2(hA.y, w0, acc[g][1][0]);
                acc[g][1][1] = fma2(hA.y, w1, acc[g][1][1]);
                acc[g][1][2] = fma2(hA.y, w2, acc[g][1][2]);
                acc[g][1][3] = fma2(hA.y, w3, acc[g][1][3]);
                acc[g][2][0] = fma2(hB.x, w0, acc[g][2][0]);
                acc[g][2][1] = fma2(hB.x, w1, acc[g][2][1]);
                acc[g][2][2] = fma2(hB.x, w2, acc[g][2][2]);
                acc[g][2][3] = fma2(hB.x, w3, acc[g][2][3]);
                acc[g][3][0] = fma2(hB.y, w0, acc[g][3][0]);
                acc[g][3][1] = fma2(hB.y, w1, acc[g][3][1]);
                acc[g][3][2] = fma2(hB.y, w2, acc[g][3][2]);
                acc[g][3][3] = fma2(hB.y, w3, acc[g][3][3]);
            }
        }

        // --- elementwise LSTM update; write h_new into the other buffer ---
        int hnxt = hcur ^ 1;
        float* hw = sH + hnxt * HBUF;
        #pragma unroll
        for (int j = 0; j < 4; ++j) {
            float hv[8];
            #pragma unroll
            for (int mp = 0; mp < 4; ++mp) {
                float i0, i1, f0, f1, g0, g1, o0, o1;
                unpack2(acc[0][mp][j], i0, i1);
                unpack2(acc[1][mp][j], f0, f1);
                unpack2(acc[2][mp][j], g0, g1);
                unpack2(acc[3][mp][j], o0, o1);
                {
                    float cn = fsig(f0) * cc[2 * mp][j] + fsig(i0) * ftanh(g0);
                    cc[2 * mp][j] = cn;
                    hv[2 * mp] = fsig(o0) * ftanh(cn);
                }
                {
                    float cn = fsig(f1) * cc[2 * mp + 1][j] + fsig(i1) * ftanh(g1);
                    cc[2 * mp + 1][j] = cn;
                    hv[2 * mp + 1] = fsig(o1) * ftanh(cn);
                }
            }
            int d = laneD + j;
            *(float4*)(hw + d * HPAD + laneM)     = make_float4(hv[0], hv[1], hv[2], hv[3]);
            *(float4*)(hw + d * HPAD + laneM + 4) = make_float4(hv[4], hv[5], hv[6], hv[7]);
        }
        hcur = hnxt;
        // next iteration's first __syncthreads orders these writes before reads
    }

    CP_WAIT0();
    __syncthreads();

    // --- write final h (coalesced along d) ---
    const float* hf = sH + hcur * HBUF;
    for (int idx = tid; idx < M_TILE * HID; idx += THREADS) {
        int m = idx >> 7, d = idx & 127;
        out[(size_t)(mBase + m) * HID + d] = hf[d * HPAD + m];
    }
}

extern "C" void kernel_launch(void* const* d_in, const int* in_sizes, int n_in,
                              void* d_out, int out_size) {
    const float* obs   = (const float*)d_in[0];
    const float* h0    = (const float*)d_in[1];
    const float* c0    = (const float*)d_in[2];
    const float* W_emb = (const float*)d_in[3];
    const float* b_emb = (const float*)d_in[4];
    const float* W_ih  = (const float*)d_in[5];
    const float* W_hh  = (const float*)d_in[6];
    const float* b_ih  = (const float*)d_in[7];
    const float* b_hh  = (const float*)d_in[8];
    float* out = (float*)d_out;

    (void)in_sizes; (void)n_in; (void)out_size;

    setup_kernel<<<256, 256>>>(W_emb, b_emb, W_ih, W_hh, b_ih, b_hh);

    cudaFuncSetAttribute(lstm_kernel, cudaFuncAttributeMaxDynamicSharedMemorySize, SMEM_BYTES);
    lstm_kernel<<<BATCH / M_TILE, THREADS, SMEM_BYTES>>>(obs, h0, c0, out);
}